// round 12
// baseline (speedup 1.0000x reference)
#include <cuda_runtime.h>
#include <cstdint>
#include <cstddef>

#define BATCH 256
#define SEQT  365
#define HID   256
#define INSZ  32
#define G4    1024          // 4*HID
#define NB    128           // persistent blocks
#define NT    256           // lstm threads: 8 warps = 2 b-halves x 4 k-quarters
#define NTX   256           // xw_kernel threads
#define NPAIR (HID / 2)     // 128 unit pairs
#define NCHUNK 16           // h chunks (16 units / 8 producer CTAs each)

typedef unsigned long long ull;

// ---------------- scratch (static device allocations; no cudaMalloc) ----------
__device__ float4 g_xw4[(size_t)SEQT * NPAIR * 2 * BATCH];   // 382 MB, bias folded
__device__ float g_hb[2][HID * BATCH];                       // h double buffer [k][b]
__device__ unsigned g_bar_count;                             // final barrier only
__device__ unsigned g_bar_gen;
__device__ unsigned g_ready[NCHUNK * 32];                    // monotonic, 128B-padded
__device__ unsigned g_cons[32];                              // monotonic, padded

// ---------------- packed f32x2 helpers ----------------------------------------
__device__ __forceinline__ ull pack2(float lo, float hi) {
    ull r;
    asm("mov.b64 %0, {%1, %2};" : "=l"(r) : "f"(lo), "f"(hi));
    return r;
}
__device__ __forceinline__ void unpack2(ull v, float& lo, float& hi) {
    asm("mov.b64 {%0, %1}, %2;" : "=f"(lo), "=f"(hi) : "l"(v));
}
__device__ __forceinline__ ull fma2(ull a, ull b, ull c) {
    ull d;
    asm("fma.rn.f32x2 %0, %1, %2, %3;" : "=l"(d) : "l"(a), "l"(b), "l"(c));
    return d;
}
__device__ __forceinline__ ull add2(ull a, ull b) {
    ull d;
    asm("add.rn.f32x2 %0, %1, %2;" : "=l"(d) : "l"(a), "l"(b));
    return d;
}
__device__ __forceinline__ float sigf(float x) {
    return __fdividef(1.0f, 1.0f + __expf(-x));
}
__device__ __forceinline__ float tanhf_fast(float x) {
    float e = __expf(2.0f * x);
    return 1.0f - __fdividef(2.0f, e + 1.0f);
}
__device__ __forceinline__ unsigned swz(unsigned off) {
    return off ^ ((off >> 3) & 0x70);
}

// ---------------- acquire/release message passing -----------------------------
__device__ __forceinline__ unsigned ld_acq(const unsigned* p) {
    unsigned v;
    asm volatile("ld.acquire.gpu.global.u32 %0, [%1];" : "=r"(v) : "l"(p) : "memory");
    return v;
}
__device__ __forceinline__ void red_add(unsigned* p, unsigned v) {
    asm volatile("red.release.gpu.global.add.u32 [%0], %1;" :: "l"(p), "r"(v) : "memory");
}

// ---------------- final grid barrier (replay-safe R7 pattern) ------------------
__device__ __forceinline__ void grid_barrier() {
    __syncthreads();
    if (threadIdx.x == 0) {
        volatile unsigned* genp = &g_bar_gen;
        unsigned gen = *genp;
        __threadfence();
        if (atomicAdd(&g_bar_count, 1u) == NB - 1u) {
            g_bar_count = 0;
            __threadfence();
            *genp = gen + 1u;
        } else {
            while (*genp == gen) { }
        }
    }
    __syncthreads();
}

// ============================================================================
// Kernel A: xw. grid (SEQT, 8); block = one t, a 32-unit tile (16 pairs).
// ============================================================================
__global__ void __launch_bounds__(NTX) xw_kernel(const float* __restrict__ x,
                                                 const float* __restrict__ w_ih,
                                                 const float* __restrict__ bias) {
    __shared__ float ws[INSZ][16][8];
    const int t   = blockIdx.x;
    const int u00 = blockIdx.y * 32;
    const int tid = threadIdx.x;

    for (int i = tid; i < INSZ * 128; i += NTX) {
        int k = i >> 7, r = i & 127, p = r >> 3, c = r & 7;
        int unit = u00 + 2 * p + (c & 1);
        ws[k][p][c] = w_ih[(size_t)k * G4 + (c >> 1) * HID + unit];
    }
    __syncthreads();

    const int b = tid;
    ull xk2[INSZ];
    const float4* xp = (const float4*)(x + ((size_t)b * SEQT + t) * INSZ);
#pragma unroll
    for (int q = 0; q < INSZ / 4; q++) {
        float4 v = xp[q];
        xk2[4 * q + 0] = pack2(v.x, v.x);
        xk2[4 * q + 1] = pack2(v.y, v.y);
        xk2[4 * q + 2] = pack2(v.z, v.z);
        xk2[4 * q + 3] = pack2(v.w, v.w);
    }

    for (int p = 0; p < 16; p++) {
        int u = u00 + 2 * p;
        ull aF = pack2(bias[u],           bias[u + 1]);
        ull aI = pack2(bias[HID + u],     bias[HID + u + 1]);
        ull aO = pack2(bias[2 * HID + u], bias[2 * HID + u + 1]);
        ull aG = pack2(bias[3 * HID + u], bias[3 * HID + u + 1]);
#pragma unroll
        for (int k = 0; k < INSZ; k++) {
            ulonglong2 wA = *(const ulonglong2*)(&ws[k][p][0]);
            ulonglong2 wB = *(const ulonglong2*)(&ws[k][p][4]);
            aF = fma2(xk2[k], wA.x, aF);
            aI = fma2(xk2[k], wA.y, aI);
            aO = fma2(xk2[k], wB.x, aO);
            aG = fma2(xk2[k], wB.y, aG);
        }
        float f0, f1, i0, i1, o0, o1, g0, g1;
        unpack2(aF, f0, f1); unpack2(aI, i0, i1);
        unpack2(aO, o0, o1); unpack2(aG, g0, g1);
        size_t base = (((size_t)t * NPAIR + (u00 / 2 + p)) * 2) * BATCH + b;
        __stcs(&g_xw4[base],         make_float4(f0, f1, i0, i1));
        __stcs(&g_xw4[base + BATCH], make_float4(o0, o1, g0, g1));
    }
}

// ============================================================================
// Kernel B: persistent LSTM (R11 compute), barrier replaced by chunk-level
// producer/consumer flags + one-step-lagged anti-overwrite gate.
// ============================================================================
__global__ void __launch_bounds__(NT, 1) lstm_kernel(const float* __restrict__ w_hh,
                                                     const float* __restrict__ fc_w,
                                                     const float* __restrict__ fc_b,
                                                     float* __restrict__ out) {
    __shared__ float ws[HID][8];
    __shared__ ull sm_part[4 * BATCH * 4];
    __shared__ float redf[NT];

    const int bid = blockIdx.x;
    const int tid = threadIdx.x;
    const int u0  = bid * 2;
    const int w   = tid >> 5;
    const int l   = tid & 31;
    const int bh  = w & 1;
    const int kh  = w >> 1;
    const int bg  = l >> 1;
    const int cg  = l & 1;
    const int b0  = bh * 128 + bg * 8;
    const int kb  = kh * 64;
    const int b   = tid;
    const int mychunk = bid >> 3;          // this CTA's h chunk (producer side)

    for (int i = tid; i < HID * 8; i += NT) {
        int k = i >> 3, c = i & 7;
        ws[k][c] = w_hh[(size_t)k * G4 + (c >> 1) * HID + u0 + (c & 1)];
    }
    __syncthreads();

    float cc0 = 0.0f, cc1 = 0.0f;

    float* outO = out;
    float* outH = out + BATCH;
    float* outC = outH + (size_t)BATCH * SEQT * HID;

    const size_t xw_stride_t = (size_t)NPAIR * 2 * BATCH;
    const float4* xwp = g_xw4 + (size_t)bid * 2 * BATCH + b;
    float4 xA = __ldcs(xwp);
    float4 xB = __ldcs(xwp + BATCH);

    const int hoff4 = bh * 32 + bg * 2;
    // each warp consumes chunks 4*kh .. 4*kh+3; lanes 0-3 poll them in parallel
    const unsigned* myready = &g_ready[(4 * kh + ((l < 4) ? l : 3)) * 32];

    for (int t = 0; t < SEQT; t++) {
        ull acc[8][2];
#pragma unroll
        for (int bb = 0; bb < 8; bb++) { acc[bb][0] = 0; acc[bb][1] = 0; }

        if (t > 0) {
            // ---- wait for this warp's 4 h chunks (producers' step t-1) ----
            {
                const unsigned tgt = 8u * (unsigned)t;
                for (;;) {
                    bool ok = (l >= 4) || (ld_acq(myready) >= tgt);
                    if (__all_sync(0xffffffffu, ok)) break;
                }
            }

            const float4* hp4 = (const float4*)g_hb[t & 1] + hoff4;
            float4 hA[2][4], hB[2][4];
#pragma unroll
            for (int j = 0; j < 4; j++) {
                hA[0][j] = __ldcg(hp4 + (size_t)(kb + j) * 64);
                hB[0][j] = __ldcg(hp4 + (size_t)(kb + j) * 64 + 1);
            }
#pragma unroll
            for (int ch = 0; ch < 16; ch++) {
                const int cur = ch & 1, nxt = cur ^ 1;
                if (ch < 15) {
#pragma unroll
                    for (int j = 0; j < 4; j++) {
                        hA[nxt][j] = __ldcg(hp4 + (size_t)(kb + (ch + 1) * 4 + j) * 64);
                        hB[nxt][j] = __ldcg(hp4 + (size_t)(kb + (ch + 1) * 4 + j) * 64 + 1);
                    }
                }
#pragma unroll
                for (int j = 0; j < 4; j++) {
                    const int k = kb + ch * 4 + j;
                    ulonglong2 wv = *(const ulonglong2*)(&ws[k][cg * 4]);
                    float4 va = hA[cur][j], vb = hB[cur][j];
                    ull h2;
                    h2 = pack2(va.x, va.x);
                    acc[0][0] = fma2(h2, wv.x, acc[0][0]);
                    acc[0][1] = fma2(h2, wv.y, acc[0][1]);
                    h2 = pack2(va.y, va.y);
                    acc[1][0] = fma2(h2, wv.x, acc[1][0]);
                    acc[1][1] = fma2(h2, wv.y, acc[1][1]);
                    h2 = pack2(va.z, va.z);
                    acc[2][0] = fma2(h2, wv.x, acc[2][0]);
                    acc[2][1] = fma2(h2, wv.y, acc[2][1]);
                    h2 = pack2(va.w, va.w);
                    acc[3][0] = fma2(h2, wv.x, acc[3][0]);
                    acc[3][1] = fma2(h2, wv.y, acc[3][1]);
                    h2 = pack2(vb.x, vb.x);
                    acc[4][0] = fma2(h2, wv.x, acc[4][0]);
                    acc[4][1] = fma2(h2, wv.y, acc[4][1]);
                    h2 = pack2(vb.y, vb.y);
                    acc[5][0] = fma2(h2, wv.x, acc[5][0]);
                    acc[5][1] = fma2(h2, wv.y, acc[5][1]);
                    h2 = pack2(vb.z, vb.z);
                    acc[6][0] = fma2(h2, wv.x, acc[6][0]);
                    acc[6][1] = fma2(h2, wv.y, acc[6][1]);
                    h2 = pack2(vb.w, vb.w);
                    acc[7][0] = fma2(h2, wv.x, acc[7][0]);
                    acc[7][1] = fma2(h2, wv.y, acc[7][1]);
                }
            }
        }

        // ---- store partials (swizzled) ----
#pragma unroll
        for (int bb = 0; bb < 8; bb++) {
            unsigned off = (unsigned)(((kh * 256 + b0 + bb) * 4 + cg * 2) * 8);
            *(ulonglong2*)((char*)sm_part + swz(off)) =
                make_ulonglong2(acc[bb][0], acc[bb][1]);
        }
        __syncthreads();

        // ---- signal: this CTA's reads of buffer (t&1) are complete ----
        if (tid == 0) {
            __threadfence();
            red_add(&g_cons[0], 1u);
        }

        // ---- activation phase: thread = batch b ----
        ull aF = pack2(xA.x, xA.y);
        ull aI = pack2(xA.z, xA.w);
        ull aO = pack2(xB.x, xB.y);
        ull aG = pack2(xB.z, xB.w);
        if (t + 1 < SEQT) {
            const float4* nx = xwp + (size_t)(t + 1) * xw_stride_t;
            xA = __ldcs(nx);
            xB = __ldcs(nx + BATCH);
        }
#pragma unroll
        for (int q = 0; q < 4; q++) {
            unsigned off = (unsigned)(((q * 256 + b) * 4) * 8);
            ulonglong2 v0 = *(const ulonglong2*)((const char*)sm_part + swz(off));
            ulonglong2 v1 = *(const ulonglong2*)((const char*)sm_part + swz(off + 16));
            aF = add2(aF, v0.x);
            aI = add2(aI, v0.y);
            aO = add2(aO, v1.x);
            aG = add2(aG, v1.y);
        }

        float f0, f1, i0, i1, o0, o1, gg0, gg1;
        unpack2(aF, f0, f1); unpack2(aI, i0, i1);
        unpack2(aO, o0, o1); unpack2(aG, gg0, gg1);

        cc0 = sigf(f0) * cc0 + sigf(i0) * tanhf_fast(gg0);
        cc1 = sigf(f1) * cc1 + sigf(i1) * tanhf_fast(gg1);
        float h0 = sigf(o0) * tanhf_fast(cc0);
        float h1 = sigf(o1) * tanhf_fast(cc1);

        // ---- anti-overwrite gate: all CTAs must have consumed step t-1
        //      before we overwrite buffer (t+1)&1 (== (t-1)&1). One-step slack. ----
        if (t > 0) {
            if (tid == 0) {
                const unsigned tgt = (unsigned)NB * (unsigned)t;
                while (ld_acq(&g_cons[0]) < tgt) { }
            }
            __syncthreads();
        }

        // ---- h exchange store ----
        float* hw = g_hb[(t + 1) & 1];
        hw[u0 * BATCH + b]       = h0;
        hw[(u0 + 1) * BATCH + b] = h1;

        // ---- publish chunk: drain stores, fence, release-increment ----
        __syncthreads();
        if (tid == 0) {
            __threadfence();
            red_add(&g_ready[mychunk * 32], 1u);
        }

        // ---- output stores overlap consumers' polling ----
        size_t ob = ((size_t)b * SEQT + t) * HID + u0;
        __stcs((float2*)(outH + ob), make_float2(h0, h1));
        __stcs((float2*)(outC + ob), make_float2(cc0, cc1));
    }

    // ---- full barrier: all final h stores visible, pipeline drained ----
    grid_barrier();

    // ---- final FC: out[bo] = h_last[bo,:] . fc_w + fc_b ----
    const float* hl = g_hb[SEQT & 1];
    float fw = fc_w[tid];
    float fb = fc_b[0];
    for (int bb = 0; bb < 2; bb++) {
        int bo = u0 + bb;
        redf[tid] = __ldcg(hl + tid * BATCH + bo) * fw;
        __syncthreads();
        for (int s = NT / 2; s > 0; s >>= 1) {
            if (tid < s) redf[tid] += redf[tid + s];
            __syncthreads();
        }
        if (tid == 0) outO[bo] = redf[0] + fb;
        __syncthreads();
    }

    // ---- reset monotonic counters for the next graph replay (CTA 0 only;
    //      no counter is read after grid_barrier in this launch) ----
    if (bid == 0) {
        for (int i = tid; i < NCHUNK * 32; i += NT) g_ready[i] = 0;
        if (tid == 0) g_cons[0] = 0;
    }
}

// ============================================================================
extern "C" void kernel_launch(void* const* d_in, const int* in_sizes, int n_in,
                              void* d_out, int out_size) {
    const float* x    = (const float*)d_in[0];
    const float* w_ih = (const float*)d_in[1];
    const float* w_hh = (const float*)d_in[2];
    const float* bias = (const float*)d_in[3];
    const float* fc_w = (const float*)d_in[4];
    const float* fc_b = (const float*)d_in[5];
    float* out = (float*)d_out;

    dim3 gA(SEQT, 8);
    xw_kernel<<<gA, NTX>>>(x, w_ih, bias);
    lstm_kernel<<<NB, NT>>>(w_hh, fc_w, fc_b, out);
}

// round 13
// speedup vs baseline: 1.1643x; 1.1643x over previous
#include <cuda_runtime.h>
#include <cstdint>
#include <cstddef>

#define BATCH 256
#define SEQT  365
#define HID   256
#define INSZ  32
#define G4    1024          // 4*HID
#define NB    128           // persistent blocks
#define NT    256
#define NTX   256
#define NPAIR (HID / 2)     // 128 unit pairs (xw layout)
#define NGRP  4             // independent batch groups
#define CPG   32            // CTAs per group
#define BPG   64            // batches per group
#define UPC   8             // units per CTA

typedef unsigned long long ull;

// ---------------- scratch (static device allocations; no cudaMalloc) ----------
__device__ float4 g_xw4[(size_t)SEQT * NPAIR * 2 * BATCH];   // 382 MB, bias folded
__device__ float g_hb[2][NGRP][HID * BPG];                   // h, [buf][grp][k][b]
__device__ unsigned g_cnt[NGRP * 32];                        // per-group barrier
__device__ unsigned g_gen[NGRP * 32];

// ---------------- packed f32x2 helpers ----------------------------------------
__device__ __forceinline__ ull pack2(float lo, float hi) {
    ull r;
    asm("mov.b64 %0, {%1, %2};" : "=l"(r) : "f"(lo), "f"(hi));
    return r;
}
__device__ __forceinline__ void unpack2(ull v, float& lo, float& hi) {
    asm("mov.b64 {%0, %1}, %2;" : "=f"(lo), "=f"(hi) : "l"(v));
}
__device__ __forceinline__ ull fma2(ull a, ull b, ull c) {
    ull d;
    asm("fma.rn.f32x2 %0, %1, %2, %3;" : "=l"(d) : "l"(a), "l"(b), "l"(c));
    return d;
}
__device__ __forceinline__ ull add2(ull a, ull b) {
    ull d;
    asm("add.rn.f32x2 %0, %1, %2;" : "=l"(d) : "l"(a), "l"(b));
    return d;
}
__device__ __forceinline__ float sigf(float x) {
    return __fdividef(1.0f, 1.0f + __expf(-x));
}
__device__ __forceinline__ float tanhf_fast(float x) {
    float e = __expf(2.0f * x);
    return 1.0f - __fdividef(2.0f, e + 1.0f);
}
__device__ __forceinline__ unsigned swz(unsigned off) {
    return off ^ ((off >> 3) & 0x70);
}

// ============================================================================
// Kernel A: xw (unchanged, R11-proven). grid (SEQT, 8).
// Layout g_xw4[t][pair][slot][b]: slot0=(f0,f1,i0,i1), slot1=(o0,o1,g0,g1).
// ============================================================================
__global__ void __launch_bounds__(NTX) xw_kernel(const float* __restrict__ x,
                                                 const float* __restrict__ w_ih,
                                                 const float* __restrict__ bias) {
    __shared__ float ws[INSZ][16][8];
    const int t   = blockIdx.x;
    const int u00 = blockIdx.y * 32;
    const int tid = threadIdx.x;

    for (int i = tid; i < INSZ * 128; i += NTX) {
        int k = i >> 7, r = i & 127, p = r >> 3, c = r & 7;
        int unit = u00 + 2 * p + (c & 1);
        ws[k][p][c] = w_ih[(size_t)k * G4 + (c >> 1) * HID + unit];
    }
    __syncthreads();

    const int b = tid;
    ull xk2[INSZ];
    const float4* xp = (const float4*)(x + ((size_t)b * SEQT + t) * INSZ);
#pragma unroll
    for (int q = 0; q < INSZ / 4; q++) {
        float4 v = xp[q];
        xk2[4 * q + 0] = pack2(v.x, v.x);
        xk2[4 * q + 1] = pack2(v.y, v.y);
        xk2[4 * q + 2] = pack2(v.z, v.z);
        xk2[4 * q + 3] = pack2(v.w, v.w);
    }

    for (int p = 0; p < 16; p++) {
        int u = u00 + 2 * p;
        ull aF = pack2(bias[u],           bias[u + 1]);
        ull aI = pack2(bias[HID + u],     bias[HID + u + 1]);
        ull aO = pack2(bias[2 * HID + u], bias[2 * HID + u + 1]);
        ull aG = pack2(bias[3 * HID + u], bias[3 * HID + u + 1]);
#pragma unroll
        for (int k = 0; k < INSZ; k++) {
            ulonglong2 wA = *(const ulonglong2*)(&ws[k][p][0]);
            ulonglong2 wB = *(const ulonglong2*)(&ws[k][p][4]);
            aF = fma2(xk2[k], wA.x, aF);
            aI = fma2(xk2[k], wA.y, aI);
            aO = fma2(xk2[k], wB.x, aO);
            aG = fma2(xk2[k], wB.y, aG);
        }
        float f0, f1, i0, i1, o0, o1, g0, g1;
        unpack2(aF, f0, f1); unpack2(aI, i0, i1);
        unpack2(aO, o0, o1); unpack2(aG, g0, g1);
        size_t base = (((size_t)t * NPAIR + (u00 / 2 + p)) * 2) * BATCH + b;
        __stcs(&g_xw4[base],         make_float4(f0, f1, i0, i1));
        __stcs(&g_xw4[base + BATCH], make_float4(o0, o1, g0, g1));
    }
}

// ============================================================================
// Kernel B: persistent LSTM. 4 independent groups x 32 CTAs.
// CTA (grp = bid>>5, ug = bid&31): units u_base = ug*8 (4 unit-pairs),
// batches grp*64..+64. Weights in SMEM ws[k][p] ull, p = up*4 + gate.
// Compute: warp (kh = w>>1, bh = w&1); lane (bg = l>>2 -> 4 batches, cg = l&3
//   -> unit-pair). Per k: 2 LDS.128 (4 gate pairs) + 1 LDG.128 (4 batches' h)
//   -> 16 fma2. acc[batch j][gate g].
// Reduce kh via swizzled SMEM; activation thread = (b = tid>>2, up = tid&3).
// ============================================================================
__global__ void __launch_bounds__(NT, 1) lstm_kernel(const float* __restrict__ w_hh,
                                                     const float* __restrict__ fc_w,
                                                     const float* __restrict__ fc_b,
                                                     float* __restrict__ out) {
    extern __shared__ char sm[];
    ull*   ws_u    = (ull*)sm;                 // [256 k][16 p], 32 KB
    ull*   sm_part = (ull*)(sm + 32768);       // [kh][b 64][p 16], 32 KB
    float* redf    = (float*)(sm + 65536);     // 1 KB

    const int bid  = blockIdx.x;
    const int grp  = bid >> 5;
    const int ug   = bid & 31;
    const int u_base = ug * UPC;
    const int tid  = threadIdx.x;
    const int l    = tid & 31;
    const int w    = tid >> 5;
    const int kh   = w >> 1;             // k-quarter
    const int bh   = w & 1;              // batch half (32)
    const int bg   = l >> 2;             // 0..7 (4-batch group)
    const int cg   = l & 3;              // 0..3 (unit-pair, compute)
    const int b0   = bh * 32 + bg * 4;   // lane's first local batch
    const int kb   = kh * 64;
    // activation mapping
    const int b_l  = tid >> 2;           // local batch 0..63
    const int up   = tid & 3;            // unit-pair 0..3
    const int u0   = u_base + up * 2;
    const int b_g  = grp * BPG + b_l;    // global batch

    // ---- weights: ws[k][up*4+g] = (w_hh[k][g*256+u0], w_hh[k][g*256+u0+1]) ----
    {
        float* ws_f = (float*)ws_u;
        for (int i = tid; i < HID * 32; i += NT) {
            int k = i >> 5, c = i & 31;               // c = up*8 + g*2 + e
            ws_f[i] = w_hh[(size_t)k * G4 + ((c >> 1) & 3) * HID
                           + u_base + (c >> 3) * 2 + (c & 1)];
        }
    }
    __syncthreads();

    float cc0 = 0.0f, cc1 = 0.0f;

    float* outO = out;
    float* outH = out + BATCH;
    float* outC = outH + (size_t)BATCH * SEQT * HID;

    // xw prefetch for t = 0: pair_glob = ug*4 + up
    const size_t xw_stride_t = (size_t)NPAIR * 2 * BATCH;
    const float4* xwp = g_xw4 + (size_t)(ug * 4 + up) * 2 * BATCH + b_g;
    float4 xA = __ldcs(xwp);
    float4 xB = __ldcs(xwp + BATCH);

    const int hoff4 = bh * 8 + bg;       // float4 index of lane's 4 batches

    for (int t = 0; t < SEQT; t++) {
        ull acc[4][4];
#pragma unroll
        for (int j = 0; j < 4; j++)
#pragma unroll
            for (int g = 0; g < 4; g++) acc[j][g] = 0;

        if (t > 0) {
            const float4* hp4 = (const float4*)g_hb[t & 1][grp] + hoff4;
            float4 hb4[2][4];
#pragma unroll
            for (int kk = 0; kk < 4; kk++)
                hb4[0][kk] = __ldcg(hp4 + (size_t)(kb + kk) * 16);
#pragma unroll
            for (int ch = 0; ch < 16; ch++) {        // 16 chunks x 4 k
                const int cur = ch & 1, nxt = cur ^ 1;
                if (ch < 15) {
#pragma unroll
                    for (int kk = 0; kk < 4; kk++)
                        hb4[nxt][kk] = __ldcg(hp4 + (size_t)(kb + (ch + 1) * 4 + kk) * 16);
                }
#pragma unroll
                for (int kk = 0; kk < 4; kk++) {
                    const int k = kb + ch * 4 + kk;
                    const ull* wrow = ws_u + (size_t)k * 16 + cg * 4;
                    ulonglong2 wv01 = *(const ulonglong2*)wrow;        // g=0 (f), g=1 (i)
                    ulonglong2 wv23 = *(const ulonglong2*)(wrow + 2);  // g=2 (o), g=3 (g)
                    float4 hv = hb4[cur][kk];
                    ull h2;
                    h2 = pack2(hv.x, hv.x);
                    acc[0][0] = fma2(h2, wv01.x, acc[0][0]);
                    acc[0][1] = fma2(h2, wv01.y, acc[0][1]);
                    acc[0][2] = fma2(h2, wv23.x, acc[0][2]);
                    acc[0][3] = fma2(h2, wv23.y, acc[0][3]);
                    h2 = pack2(hv.y, hv.y);
                    acc[1][0] = fma2(h2, wv01.x, acc[1][0]);
                    acc[1][1] = fma2(h2, wv01.y, acc[1][1]);
                    acc[1][2] = fma2(h2, wv23.x, acc[1][2]);
                    acc[1][3] = fma2(h2, wv23.y, acc[1][3]);
                    h2 = pack2(hv.z, hv.z);
                    acc[2][0] = fma2(h2, wv01.x, acc[2][0]);
                    acc[2][1] = fma2(h2, wv01.y, acc[2][1]);
                    acc[2][2] = fma2(h2, wv23.x, acc[2][2]);
                    acc[2][3] = fma2(h2, wv23.y, acc[2][3]);
                    h2 = pack2(hv.w, hv.w);
                    acc[3][0] = fma2(h2, wv01.x, acc[3][0]);
                    acc[3][1] = fma2(h2, wv01.y, acc[3][1]);
                    acc[3][2] = fma2(h2, wv23.x, acc[3][2]);
                    acc[3][3] = fma2(h2, wv23.y, acc[3][3]);
                }
            }
        }

        // ---- store partials: sm_part[kh][b][p], swizzled ----
#pragma unroll
        for (int j = 0; j < 4; j++) {
            unsigned off = (unsigned)(((kh * 64 + b0 + j) * 16 + cg * 4) * 8);
            *(ulonglong2*)((char*)sm_part + swz(off)) =
                make_ulonglong2(acc[j][0], acc[j][1]);
            *(ulonglong2*)((char*)sm_part + swz(off + 16)) =
                make_ulonglong2(acc[j][2], acc[j][3]);
        }
        __syncthreads();

        // ---- activation: thread = (b_l, up) ----
        ull sF = 0, sI = 0, sO = 0, sG = 0;
#pragma unroll
        for (int q = 0; q < 4; q++) {
            unsigned off = (unsigned)(((q * 64 + b_l) * 16 + up * 4) * 8);
            ulonglong2 v0 = *(const ulonglong2*)((const char*)sm_part + swz(off));
            ulonglong2 v1 = *(const ulonglong2*)((const char*)sm_part + swz(off + 16));
            sF = add2(sF, v0.x);
            sI = add2(sI, v0.y);
            sO = add2(sO, v1.x);
            sG = add2(sG, v1.y);
        }
        ull aF = add2(pack2(xA.x, xA.y), sF);
        ull aI = add2(pack2(xA.z, xA.w), sI);
        ull aO = add2(pack2(xB.x, xB.y), sO);
        ull aG = add2(pack2(xB.z, xB.w), sG);

        if (t + 1 < SEQT) {
            const float4* nx = xwp + (size_t)(t + 1) * xw_stride_t;
            xA = __ldcs(nx);
            xB = __ldcs(nx + BATCH);
        }

        float f0, f1, i0, i1, o0, o1, gg0, gg1;
        unpack2(aF, f0, f1); unpack2(aI, i0, i1);
        unpack2(aO, o0, o1); unpack2(aG, gg0, gg1);

        cc0 = sigf(f0) * cc0 + sigf(i0) * tanhf_fast(gg0);
        cc1 = sigf(f1) * cc1 + sigf(i1) * tanhf_fast(gg1);
        float h0 = sigf(o0) * tanhf_fast(cc0);
        float h1 = sigf(o1) * tanhf_fast(cc1);

        // ---- h exchange store (group-local) ----
        float* hw = g_hb[(t + 1) & 1][grp];
        hw[u0 * BPG + b_l]       = h0;
        hw[(u0 + 1) * BPG + b_l] = h1;

        // ---- ARRIVE early on the 32-CTA group barrier ----
        __syncthreads();
        unsigned my_gen = 0;
        bool releaser = false;
        if (tid == 0) {
            volatile unsigned* genp = &g_gen[grp * 32];
            my_gen = *genp;
            __threadfence();
            if (atomicAdd(&g_cnt[grp * 32], 1u) == CPG - 1u) {
                g_cnt[grp * 32] = 0;
                __threadfence();
                *genp = my_gen + 1u;
                releaser = true;
            }
        }

        // ---- output stores overlap the barrier wait ----
        size_t ob = ((size_t)b_g * SEQT + t) * HID + u0;
        __stcs((float2*)(outH + ob), make_float2(h0, h1));
        __stcs((float2*)(outC + ob), make_float2(cc0, cc1));

        // ---- WAIT ----
        if (tid == 0 && !releaser) {
            volatile unsigned* genp = &g_gen[grp * 32];
            while (*genp == my_gen) { }
        }
        __syncthreads();
    }

    // ---- final FC: CTA handles local batches ug*2, ug*2+1 of its group ----
    const float* hl = g_hb[SEQT & 1][grp];
    float fw = fc_w[tid];
    float fb = fc_b[0];
    for (int bb = 0; bb < 2; bb++) {
        int bo = ug * 2 + bb;                      // local batch
        redf[tid] = __ldcg(hl + (size_t)tid * BPG + bo) * fw;   // k = tid
        __syncthreads();
        for (int s = NT / 2; s > 0; s >>= 1) {
            if (tid < s) redf[tid] += redf[tid + s];
            __syncthreads();
        }
        if (tid == 0) outO[grp * BPG + bo] = redf[0] + fb;
        __syncthreads();
    }
}

// ============================================================================
extern "C" void kernel_launch(void* const* d_in, const int* in_sizes, int n_in,
                              void* d_out, int out_size) {
    const float* x    = (const float*)d_in[0];
    const float* w_ih = (const float*)d_in[1];
    const float* w_hh = (const float*)d_in[2];
    const float* bias = (const float*)d_in[3];
    const float* fc_w = (const float*)d_in[4];
    const float* fc_b = (const float*)d_in[5];
    float* out = (float*)d_out;

    static int configured = 0;
    if (!configured) {
        cudaFuncSetAttribute(lstm_kernel, cudaFuncAttributeMaxDynamicSharedMemorySize, 66560);
        configured = 1;
    }

    dim3 gA(SEQT, 8);
    xw_kernel<<<gA, NTX>>>(x, w_ih, bias);
    lstm_kernel<<<NB, NT, 66560>>>(w_hh, fc_w, fc_b, out);
}